// round 16
// baseline (speedup 1.0000x reference)
#include <cuda_runtime.h>
#include <cuda_bf16.h>
#include <cuda_fp16.h>
#include <cstdint>

// Problem constants (fixed shapes)
#define BB 2
#define NN 2048
#define CC 1024
#define HH 16
#define HD 64
#define MM (BB * NN)   // 4096 rows

// q pre-scale: 0.125 (hd^-0.5) * log2(e)  -> S comes out in log2 units
#define QSCALE 0.1803368801111137f

typedef __half f16;

// ---------------------------------------------------------------------------
// Scratch (device globals — no allocations allowed)
// ---------------------------------------------------------------------------
__device__ float g_ao[MM * CC];
__device__ f16 g_xf[MM * CC];                  // LN output, fp16
__device__ f16 g_qkh[MM * 2 * CC];             // q|k fp16 (q pre-scaled QSCALE)
__device__ f16 g_v[MM * CC];                   // v fp16
__device__ f16 g_wT[3 * CC * CC];              // fused w^T fp16: qk rows [0,2C), v rows [2C,3C)
__device__ f16 g_wpT[CC * CC];                 // w_proj^T fp16

// ---------------------------------------------------------------------------
// helpers
// ---------------------------------------------------------------------------
__device__ __forceinline__ uint32_t smem_u32(const void* p) {
    uint32_t a;
    asm("{ .reg .u64 t; cvta.to.shared.u64 t, %1; cvt.u32.u64 %0, t; }"
        : "=r"(a) : "l"(p));
    return a;
}

__device__ __forceinline__ void mma_f16(float* c, const unsigned* a, const unsigned* b) {
    asm volatile(
        "mma.sync.aligned.m16n8k16.row.col.f32.f16.f16.f32 "
        "{%0,%1,%2,%3}, {%4,%5,%6,%7}, {%8,%9}, {%0,%1,%2,%3};"
        : "+f"(c[0]), "+f"(c[1]), "+f"(c[2]), "+f"(c[3])
        : "r"(a[0]), "r"(a[1]), "r"(a[2]), "r"(a[3]), "r"(b[0]), "r"(b[1]));
}

__device__ __forceinline__ void ldm_x4(unsigned* r, uint32_t addr) {
    asm volatile("ldmatrix.sync.aligned.m8n8.x4.shared.b16 {%0,%1,%2,%3}, [%4];"
        : "=r"(r[0]), "=r"(r[1]), "=r"(r[2]), "=r"(r[3]) : "r"(addr));
}
__device__ __forceinline__ void ldm_x4t(unsigned* r, uint32_t addr) {
    asm volatile("ldmatrix.sync.aligned.m8n8.x4.trans.shared.b16 {%0,%1,%2,%3}, [%4];"
        : "=r"(r[0]), "=r"(r[1]), "=r"(r[2]), "=r"(r[3]) : "r"(addr));
}

// cp.async 16B global -> shared
__device__ __forceinline__ void cp16(uint32_t dst, const void* src) {
    asm volatile("cp.async.cg.shared.global [%0], [%1], 16;"
        :: "r"(dst), "l"(__cvta_generic_to_global(src)) : "memory");
}
#define CP_COMMIT() asm volatile("cp.async.commit_group;" ::: "memory")
#define CP_WAIT2()  asm volatile("cp.async.wait_group 2;" ::: "memory")
#define CP_WAIT1()  asm volatile("cp.async.wait_group 1;" ::: "memory")
#define CP_WAIT0()  asm volatile("cp.async.wait_group 0;" ::: "memory")

// pack two f32 -> f16x2 register (lo = first arg)
__device__ __forceinline__ unsigned pack_f162(float lo, float hi) {
    unsigned r;
    asm("cvt.rn.f16x2.f32 %0, %1, %2;" : "=r"(r) : "f"(hi), "f"(lo));
    return r;
}
__device__ __forceinline__ unsigned hsub2(unsigned a, unsigned b) {
    unsigned r;
    asm("sub.f16x2 %0, %1, %2;" : "=r"(r) : "r"(a), "r"(b));
    return r;
}
__device__ __forceinline__ unsigned ex2_f16x2(unsigned a) {
    unsigned r;
    asm("ex2.approx.f16x2 %0, %1;" : "=r"(r) : "r"(a));
    return r;
}

// ---------------------------------------------------------------------------
// LayerNorm -> fp16: warp-per-row, pure shuffle reduce
// ---------------------------------------------------------------------------
__global__ void ln_f16_kernel(const float* __restrict__ x,
                              const float* __restrict__ g,
                              const float* __restrict__ b,
                              f16* __restrict__ o) {
    int warp = threadIdx.x >> 5, lane = threadIdx.x & 31;
    int row = blockIdx.x * 4 + warp;
    const float4* xr = reinterpret_cast<const float4*>(x + (size_t)row * CC);

    float4 v[8];
    float s = 0.0f, ss = 0.0f;
    #pragma unroll
    for (int j = 0; j < 8; j++) {
        v[j] = xr[lane + j * 32];
        s  += v[j].x + v[j].y + v[j].z + v[j].w;
        ss += v[j].x * v[j].x + v[j].y * v[j].y + v[j].z * v[j].z + v[j].w * v[j].w;
    }
    #pragma unroll
    for (int of = 16; of > 0; of >>= 1) {
        s  += __shfl_xor_sync(0xFFFFFFFFu, s,  of);
        ss += __shfl_xor_sync(0xFFFFFFFFu, ss, of);
    }

    float mu  = s * (1.0f / CC);
    float var = ss * (1.0f / CC) - mu * mu;
    float inv = rsqrtf(var + 1e-5f);

    const float4* gr = reinterpret_cast<const float4*>(g);
    const float4* br = reinterpret_cast<const float4*>(b);
    uint2* op = reinterpret_cast<uint2*>(o + (size_t)row * CC);
    #pragma unroll
    for (int j = 0; j < 8; j++) {
        float4 gv = gr[lane + j * 32];
        float4 bv = br[lane + j * 32];
        float o0 = (v[j].x - mu) * inv * gv.x + bv.x;
        float o1 = (v[j].y - mu) * inv * gv.y + bv.y;
        float o2 = (v[j].z - mu) * inv * gv.z + bv.z;
        float o3 = (v[j].w - mu) * inv * gv.w + bv.w;
        op[lane + j * 32] = make_uint2(pack_f162(o0, o1), pack_f162(o2, o3));
    }
}

// ---------------------------------------------------------------------------
// Transpose: w[K][N] fp32 -> wT[N][K] fp16
// ---------------------------------------------------------------------------
__global__ void wsplit_f16(const float* __restrict__ w,
                           f16* __restrict__ tOut,
                           int K, int N) {
    __shared__ float t[32][33];
    int bx = blockIdx.x, by = blockIdx.y;
    int x = bx * 32 + threadIdx.x;
    #pragma unroll
    for (int j = 0; j < 32; j += 8)
        t[threadIdx.y + j][threadIdx.x] = w[(size_t)(by * 32 + threadIdx.y + j) * N + x];
    __syncthreads();
    int n = bx * 32 + threadIdx.y;
    int k = by * 32 + threadIdx.x;
    #pragma unroll
    for (int j = 0; j < 32; j += 8)
        tOut[(size_t)(n + j) * K + k] = __float2half(t[threadIdx.x][threadIdx.y + j]);
}

// ---------------------------------------------------------------------------
// 1-pass fp16 GEMM (fp32 accumulate): C[M,N] = A[M,K] @ B[N,K]^T.
// MODE 0: fp32 out (+bias). MODE 2: fused qkv epilogue — cols [0,2C) -> Cq
// (xQSCALE for cols < C), cols [2C,3C) -> Cv at col-2C.
// CTA 128x128 tile, 8 warps (2x4), warp 64x32. K chunk 64.
// 4-stage cp.async ring, ONE __syncthreads per chunk:
//   buffer c&3 is overwritten by issue(c+4) at iteration c+2, which every
//   warp reaches only after sync_{c+1}, and sync_{c+1} globally orders after
//   compute(c) (compute(c) precedes iteration c+1 in program order).
// Same ascending k16 accumulation order -> bit-identical results.
// ---------------------------------------------------------------------------
#define KCG 64
#define PADG 72
#define SBUF (128 * PADG)          // f16 elems per tensor-buffer
#define GSMEM (8 * SBUF * 2)       // bytes (147456) — 4 stages x (A,B)

template <int MODE>
__global__ void __launch_bounds__(256)
gemm_f16(const f16* __restrict__ A, const f16* __restrict__ B,
         const float* __restrict__ bias, float* __restrict__ C,
         f16* __restrict__ Cq, f16* __restrict__ Cv,
         int M, int N, int K) {
    extern __shared__ f16 gsm[];
    const uint32_t sbase = smem_u32(gsm);

    int tid = threadIdx.x;
    int warp = tid >> 5, lane = tid & 31;
    int wm = warp >> 2, wn = warp & 3;
    int m0 = blockIdx.y * 128, n0 = blockIdx.x * 128;

    // cp.async mapping: 4 rows per thread per tensor (row = (tid>>3)+p*32)
    int lr = tid >> 3, lc = (tid & 7) * 8;

    float acc[4][4][4];
    #pragma unroll
    for (int i = 0; i < 4; i++)
        #pragma unroll
        for (int j = 0; j < 4; j++)
            #pragma unroll
            for (int q = 0; q < 4; q++) acc[i][j][q] = 0.0f;

    int a_row = wm * 64 + (lane & 15);
    int a_cb  = ((lane >> 4) & 1) * 16;
    int b_row = wn * 32 + ((lane >> 4) & 1) * 8 + (lane & 7);
    int b_cb  = ((lane >> 3) & 1) * 16;

    auto issue = [&](int c, int buf) {
        uint32_t bA = sbase + (uint32_t)(2 * buf) * (SBUF * 2);
        uint32_t bB = sbase + (uint32_t)(2 * buf + 1) * (SBUF * 2);
        #pragma unroll
        for (int p = 0; p < 4; p++) {
            int r = lr + p * 32;
            uint32_t so = (uint32_t)(r * PADG + lc) * 2;
            cp16(bA + so, A + (size_t)(m0 + r) * K + c * KCG + lc);
            cp16(bB + so, B + (size_t)(n0 + r) * K + c * KCG + lc);
        }
        CP_COMMIT();
    };

    issue(0, 0);
    issue(1, 1);

    int nch = K / KCG;
    #pragma unroll 1
    for (int c = 0; c < nch; c++) {
        int cur = c & 3;
        if (c + 2 < nch) {
            issue(c + 2, (c + 2) & 3);
            CP_WAIT2();
        } else if (c + 1 < nch) {
            CP_WAIT1();
        } else {
            CP_WAIT0();
        }
        __syncthreads();

        uint32_t baseA = sbase + (uint32_t)(2 * cur) * (SBUF * 2);
        uint32_t baseB = sbase + (uint32_t)(2 * cur + 1) * (SBUF * 2);

        #pragma unroll
        for (int kk = 0; kk < 4; kk++) {
            unsigned fA[4][4], fB[4][2];
            #pragma unroll
            for (int np = 0; np < 2; np++) {
                unsigned r4[4];
                uint32_t ab = baseB + (uint32_t)(b_row + np * 16) * (PADG * 2)
                              + kk * 32 + b_cb;
                ldm_x4(r4, ab);
                fB[np * 2 + 0][0] = r4[0]; fB[np * 2 + 0][1] = r4[1];
                fB[np * 2 + 1][0] = r4[2]; fB[np * 2 + 1][1] = r4[3];
            }
            #pragma unroll
            for (int mt = 0; mt < 4; mt++)
                ldm_x4(fA[mt], baseA + (uint32_t)(a_row + mt * 16) * (PADG * 2)
                                + kk * 32 + a_cb);
            #pragma unroll
            for (int mt = 0; mt < 4; mt++)
                #pragma unroll
                for (int nt = 0; nt < 4; nt++)
                    mma_f16(acc[mt][nt], fA[mt], fB[nt]);
        }
    }

    // epilogue
    #pragma unroll
    for (int mt = 0; mt < 4; mt++) {
        int row = m0 + wm * 64 + mt * 16 + (lane >> 2);
        #pragma unroll
        for (int nt = 0; nt < 4; nt++) {
            int col = n0 + wn * 32 + nt * 8 + (lane & 3) * 2;
            if (MODE == 2) {
                // fused qkv routing: [0,C)=q (xQSCALE), [C,2C)=k, [2C,3C)=v
                float sc = (col < CC) ? QSCALE : 1.0f;
                f16* dst;
                if (col < 2 * CC) dst = Cq + (size_t)row * (2 * CC) + col;
                else              dst = Cv + (size_t)row * CC + (col - 2 * CC);
                #pragma unroll
                for (int half = 0; half < 2; half++) {
                    float v0 = acc[mt][nt][half * 2 + 0] * sc;
                    float v1 = acc[mt][nt][half * 2 + 1] * sc;
                    *reinterpret_cast<unsigned*>(
                        dst + (size_t)(half * 8) * ((col < 2 * CC) ? 2 * CC : CC)) =
                        pack_f162(v0, v1);
                }
            } else {
                float bx = bias[col], by = bias[col + 1];
                float2 r0 = make_float2(acc[mt][nt][0] + bx, acc[mt][nt][1] + by);
                float2 r1 = make_float2(acc[mt][nt][2] + bx, acc[mt][nt][3] + by);
                *reinterpret_cast<float2*>(C + (size_t)row * N + col) = r0;
                *reinterpret_cast<float2*>(C + (size_t)(row + 8) * N + col) = r1;
            }
        }
    }
}

// ---------------------------------------------------------------------------
// Flash attention on tensor cores — fp16 operands, fp32 accumulate.
// log2-domain softmax (q pre-scaled 0.125*log2e), p = ex2.approx.f16x2,
// l via ones-column MMA. BQ=128, 4 warps. cp.async double buffer.
// (unchanged from R14 — at its mma.sync MMA floor)
// ---------------------------------------------------------------------------
#define APAD 72
#define KVB (2 * 64 * APAD)        // elems per K/V buffer (K | V)
#define ASMEM (2 * KVB * 2 + 16)   // bytes (+16: boundary ldmatrix guard)

__global__ void __launch_bounds__(128)
attn_mma(const f16* __restrict__ qkh, const f16* __restrict__ vp,
         float* __restrict__ out) {
    extern __shared__ f16 sm[];
    const uint32_t sb = smem_u32(sm);

    int qt = blockIdx.x, h = blockIdx.y, b = blockIdx.z;
    int tid = threadIdx.x, warp = tid >> 5, lane = tid & 31;
    int quad = lane >> 2;

    // --- stage Q (fp16, 128 rows) in smem; build persistent frags ---
    for (int i = tid; i < 128 * 8; i += 128) {
        int r = i >> 3, c8 = (i & 7) * 8;
        size_t grow = (size_t)(b * NN + qt * 128 + r) * (2 * CC) + h * HD + c8;
        *reinterpret_cast<uint4*>(&sm[r * APAD + c8]) =
            *reinterpret_cast<const uint4*>(qkh + grow);
    }
    __syncthreads();
    unsigned fQ[2][4][4];
    {
        int cb = ((lane >> 4) & 1) * 16;
        #pragma unroll
        for (int mt = 0; mt < 2; mt++) {
            int ar = warp * 32 + mt * 16 + (lane & 15);
            #pragma unroll
            for (int kk = 0; kk < 4; kk++)
                ldm_x4(fQ[mt][kk], sb + (uint32_t)(ar * APAD) * 2 + kk * 32 + cb);
        }
    }
    __syncthreads();

    // --- ones-column init: V rows col64=1.0, cols65-71=0, both buffers ---
    {
        int buf = tid >> 6, r = tid & 63;
        uint32_t addr = sb + (uint32_t)buf * (KVB * 2)
                        + (uint32_t)(64 * APAD + r * APAD + 64) * 2;
        asm volatile("st.shared.v4.b32 [%0], {%1,%2,%3,%4};"
            :: "r"(addr), "r"(0x00003C00u), "r"(0u), "r"(0u), "r"(0u) : "memory");
    }

    float O[2][8][4];
    #pragma unroll
    for (int mt = 0; mt < 2; mt++)
        #pragma unroll
        for (int nt = 0; nt < 8; nt++)
            #pragma unroll
            for (int q = 0; q < 4; q++) O[mt][nt][q] = 0.0f;
    float lacc[2][4];
    #pragma unroll
    for (int mt = 0; mt < 2; mt++)
        #pragma unroll
        for (int q = 0; q < 4; q++) lacc[mt][q] = 0.0f;
    float mS[2][2];
    #pragma unroll
    for (int mt = 0; mt < 2; mt++) { mS[mt][0] = -1e30f; mS[mt][1] = -1e30f; }

    int krow = tid >> 3, kcol = (tid & 7) * 8;

    int kb_row = ((lane >> 4) & 1) * 8 + (lane & 7);
    int kb_cb  = ((lane >> 3) & 1) * 16;
    int vb_row = ((lane >> 3) & 1) * 8 + (lane & 7);
    int vb_cb  = ((lane >> 4) & 1) * 16;

    auto kv_issue = [&](int it, int buf) {
        uint32_t base = sb + (uint32_t)buf * (KVB * 2);
        #pragma unroll
        for (int rr = 0; rr < 64; rr += 16) {
            int r = krow + rr;
            size_t gk = (size_t)(b * NN + it * 64 + r) * (2 * CC) + CC + h * HD + kcol;
            size_t gv = (size_t)(b * NN + it * 64 + r) * CC + h * HD + kcol;
            cp16(base + (uint32_t)(0 * 64 * APAD + r * APAD + kcol) * 2, qkh + gk);
            cp16(base + (uint32_t)(1 * 64 * APAD + r * APAD + kcol) * 2, vp + gv);
        }
        CP_COMMIT();
    };

    kv_issue(0, 0);

    const int NIT = NN / 64;
    #pragma unroll 1
    for (int it = 0; it < NIT; it++) {
        int cur = it & 1;
        if (it + 1 < NIT) {
            kv_issue(it + 1, cur ^ 1);
            CP_WAIT1();
        } else {
            CP_WAIT0();
        }
        __syncthreads();

        uint32_t base = sb + (uint32_t)cur * (KVB * 2);
        uint32_t sKh = base;
        uint32_t sVh = base + 1 * 64 * APAD * 2;

        // ---- S = Q @ K^T (1 pass, fp16; K frags shared across 2 m-tiles) ----
        float S[2][8][4];
        #pragma unroll
        for (int mt = 0; mt < 2; mt++)
            #pragma unroll
            for (int nt = 0; nt < 8; nt++)
                #pragma unroll
                for (int q = 0; q < 4; q++) S[mt][nt][q] = 0.0f;

        #pragma unroll
        for (int kk = 0; kk < 4; kk++) {
            unsigned fKh[8][2];
            #pragma unroll
            for (int np = 0; np < 4; np++) {
                unsigned r4[4];
                uint32_t off = (uint32_t)(kb_row + np * 16) * (APAD * 2) + kb_cb + kk * 32;
                ldm_x4(r4, sKh + off);
                fKh[np * 2 + 0][0] = r4[0]; fKh[np * 2 + 0][1] = r4[1];
                fKh[np * 2 + 1][0] = r4[2]; fKh[np * 2 + 1][1] = r4[3];
            }
            #pragma unroll
            for (int mt = 0; mt < 2; mt++)
                #pragma unroll
                for (int nt = 0; nt < 8; nt++)
                    mma_f16(S[mt][nt], fQ[mt][kk], fKh[nt]);
        }

        // ---- log2-domain softmax + fp16x2 exp + pack P ----
        unsigned Phi[2][8][2];
        #pragma unroll
        for (int mt = 0; mt < 2; mt++) {
            float mx0 = -1e30f, mx1 = -1e30f;
            #pragma unroll
            for (int nt = 0; nt < 8; nt++) {
                mx0 = fmaxf(mx0, fmaxf(S[mt][nt][0], S[mt][nt][1]));
                mx1 = fmaxf(mx1, fmaxf(S[mt][nt][2], S[mt][nt][3]));
            }
            mx0 = fmaxf(mx0, __shfl_xor_sync(0xFFFFFFFFu, mx0, 1));
            mx0 = fmaxf(mx0, __shfl_xor_sync(0xFFFFFFFFu, mx0, 2));
            mx1 = fmaxf(mx1, __shfl_xor_sync(0xFFFFFFFFu, mx1, 1));
            mx1 = fmaxf(mx1, __shfl_xor_sync(0xFFFFFFFFu, mx1, 2));
            float mn0 = fmaxf(mS[mt][0], mx0), mn1 = fmaxf(mS[mt][1], mx1);
            float al0 = exp2f(mS[mt][0] - mn0), al1 = exp2f(mS[mt][1] - mn1);
            mS[mt][0] = mn0; mS[mt][1] = mn1;

            unsigned m00 = pack_f162(mn0, mn0);
            unsigned m11 = pack_f162(mn1, mn1);

            #pragma unroll
            for (int nt = 0; nt < 8; nt++) {
                O[mt][nt][0] *= al0; O[mt][nt][1] *= al0;
                O[mt][nt][2] *= al1; O[mt][nt][3] *= al1;
            }
            lacc[mt][0] *= al0; lacc[mt][1] *= al0;
            lacc[mt][2] *= al1; lacc[mt][3] *= al1;

            #pragma unroll
            for (int nt = 0; nt < 8; nt++) {
                unsigned s01 = pack_f162(S[mt][nt][0], S[mt][nt][1]);
                unsigned s23 = pack_f162(S[mt][nt][2], S[mt][nt][3]);
                Phi[mt][nt][0] = ex2_f16x2(hsub2(s01, m00));
                Phi[mt][nt][1] = ex2_f16x2(hsub2(s23, m11));
            }
        }

        // ---- O += P @ V; l += P @ ones (fp16 MMA; V frags shared) ----
        #pragma unroll
        for (int kk = 0; kk < 4; kk++) {
            unsigned fVh[8][2], fL[2];
            #pragma unroll
            for (int nt2 = 0; nt2 < 4; nt2++) {
                unsigned r4[4];
                uint32_t off = (uint32_t)(vb_row + kk * 16) * (APAD * 2) + vb_cb + nt2 * 32;
                ldm_x4t(r4, sVh + off);
                fVh[nt2 * 2 + 0][0] = r4[0]; fVh[nt2 * 2 + 0][1] = r4[1];
                fVh[nt2 * 2 + 1][0] = r4[2]; fVh[nt2 * 2 + 1][1] = r4[3];
            }
            {
                unsigned r4[4];
                uint32_t off = (uint32_t)(vb_row + kk * 16) * (APAD * 2) + vb_cb + 4 * 32;
                ldm_x4t(r4, sVh + off);
                fL[0] = r4[0]; fL[1] = r4[1];   // cols 64-71 (ones | zeros)
            }
            #pragma unroll
            for (int mt = 0; mt < 2; mt++) {
                unsigned aPh[4] = {Phi[mt][2 * kk][0], Phi[mt][2 * kk][1],
                                   Phi[mt][2 * kk + 1][0], Phi[mt][2 * kk + 1][1]};
                #pragma unroll
                for (int nt = 0; nt < 8; nt++)
                    mma_f16(O[mt][nt], aPh, fVh[nt]);
                mma_f16(lacc[mt], aPh, fL);
            }
        }
        __syncthreads();
    }

    // ---- finalize & store (l lives in tq=0 lanes' c0/c2) ----
    #pragma unroll
    for (int mt = 0; mt < 2; mt++) {
        float l0 = __shfl_sync(0xFFFFFFFFu, lacc[mt][0], lane & 28);
        float l1 = __shfl_sync(0xFFFFFFFFu, lacc[mt][2], lane & 28);
        float inv0 = 1.0f / l0, inv1 = 1.0f / l1;
        int row0 = b * NN + qt * 128 + warp * 32 + mt * 16 + quad;
        #pragma unroll
        for (int nt = 0; nt < 8; nt++) {
            int col = h * HD + nt * 8 + (lane & 3) * 2;
            *reinterpret_cast<float2*>(out + (size_t)row0 * CC + col) =
                make_float2(O[mt][nt][0] * inv0, O[mt][nt][1] * inv0);
            *reinterpret_cast<float2*>(out + (size_t)(row0 + 8) * CC + col) =
                make_float2(O[mt][nt][2] * inv1, O[mt][nt][3] * inv1);
        }
    }
}

// ---------------------------------------------------------------------------
extern "C" void kernel_launch(void* const* d_in, const int* in_sizes, int n_in,
                              void* d_out, int out_size) {
    const float* x      = (const float*)d_in[0];
    const float* ln1_g  = (const float*)d_in[1];
    const float* ln1_b  = (const float*)d_in[2];
    const float* w_qk   = (const float*)d_in[3];
    const float* w_v    = (const float*)d_in[4];
    const float* ln2_g  = (const float*)d_in[5];
    const float* ln2_b  = (const float*)d_in[6];
    const float* w_proj = (const float*)d_in[7];
    const float* b_proj = (const float*)d_in[8];
    float* out = (float*)d_out;

    float* ao;
    f16 *xf, *qkh, *vp, *wT, *wpT;
    cudaGetSymbolAddress((void**)&ao,   g_ao);
    cudaGetSymbolAddress((void**)&xf,   g_xf);
    cudaGetSymbolAddress((void**)&qkh,  g_qkh);
    cudaGetSymbolAddress((void**)&vp,   g_v);
    cudaGetSymbolAddress((void**)&wT,   g_wT);
    cudaGetSymbolAddress((void**)&wpT,  g_wpT);

    cudaFuncSetAttribute(attn_mma, cudaFuncAttributeMaxDynamicSharedMemorySize, ASMEM);
    cudaFuncSetAttribute(gemm_f16<2>, cudaFuncAttributeMaxDynamicSharedMemorySize, GSMEM);
    cudaFuncSetAttribute(gemm_f16<0>, cudaFuncAttributeMaxDynamicSharedMemorySize, GSMEM);

    // weight transpose -> fp16 (fused buffer: qk rows [0,2C), v rows [2C,3C))
    wsplit_f16<<<dim3(2 * CC / 32, CC / 32), dim3(32, 8)>>>(w_qk, wT, CC, 2 * CC);
    wsplit_f16<<<dim3(CC / 32, CC / 32), dim3(32, 8)>>>(
        w_v, wT + (size_t)2 * CC * CC, CC, CC);
    wsplit_f16<<<dim3(CC / 32, CC / 32), dim3(32, 8)>>>(w_proj, wpT, CC, CC);

    // 1. LN1 -> fp16 (warp-per-row)
    ln_f16_kernel<<<MM / 4, 128>>>(x, ln1_g, ln1_b, xf);

    // 2. fused qkv projection (1-pass fp16; q pre-scaled by 0.125*log2e)
    gemm_f16<2><<<dim3(3 * CC / 128, MM / 128), 256, GSMEM>>>(
        xf, wT, nullptr, nullptr, qkh, vp, MM, 3 * CC, CC);

    // 3. tensor-core flash attention (log2-softmax, f16x2 exp, MMA-computed l)
    attn_mma<<<dim3(NN / 128, HH, BB), 128, ASMEM>>>(qkh, vp, ao);

    // 4. LN2 -> fp16
    ln_f16_kernel<<<MM / 4, 128>>>(ao, ln2_g, ln2_b, xf);

    // 5. output projection + bias (1-pass fp16, fp32 out)
    gemm_f16<0><<<dim3(CC / 128, MM / 128), 256, GSMEM>>>(
        xf, wpT, b_proj, out, nullptr, nullptr, MM, CC, CC);
}

// round 17
// speedup vs baseline: 1.0517x; 1.0517x over previous
#include <cuda_runtime.h>
#include <cuda_bf16.h>
#include <cuda_fp16.h>
#include <cstdint>

// Problem constants (fixed shapes)
#define BB 2
#define NN 2048
#define CC 1024
#define HH 16
#define HD 64
#define MM (BB * NN)   // 4096 rows

// q pre-scale: 0.125 (hd^-0.5) * log2(e)  -> S comes out in log2 units
#define QSCALE 0.1803368801111137f

typedef __half f16;

// ---------------------------------------------------------------------------
// Scratch (device globals — no allocations allowed)
// ---------------------------------------------------------------------------
__device__ float g_ao[MM * CC];
__device__ f16 g_xf[MM * CC];                  // LN output, fp16
__device__ f16 g_qkh[MM * 2 * CC];             // q|k fp16 (q pre-scaled QSCALE)
__device__ f16 g_v[MM * CC];                   // v fp16
__device__ f16 g_wT[3 * CC * CC];              // fused w^T fp16: qk rows [0,2C), v rows [2C,3C)
__device__ f16 g_wpT[CC * CC];                 // w_proj^T fp16

// ---------------------------------------------------------------------------
// helpers
// ---------------------------------------------------------------------------
__device__ __forceinline__ uint32_t smem_u32(const void* p) {
    uint32_t a;
    asm("{ .reg .u64 t; cvta.to.shared.u64 t, %1; cvt.u32.u64 %0, t; }"
        : "=r"(a) : "l"(p));
    return a;
}

__device__ __forceinline__ void mma_f16(float* c, const unsigned* a, const unsigned* b) {
    asm volatile(
        "mma.sync.aligned.m16n8k16.row.col.f32.f16.f16.f32 "
        "{%0,%1,%2,%3}, {%4,%5,%6,%7}, {%8,%9}, {%0,%1,%2,%3};"
        : "+f"(c[0]), "+f"(c[1]), "+f"(c[2]), "+f"(c[3])
        : "r"(a[0]), "r"(a[1]), "r"(a[2]), "r"(a[3]), "r"(b[0]), "r"(b[1]));
}

__device__ __forceinline__ void ldm_x4(unsigned* r, uint32_t addr) {
    asm volatile("ldmatrix.sync.aligned.m8n8.x4.shared.b16 {%0,%1,%2,%3}, [%4];"
        : "=r"(r[0]), "=r"(r[1]), "=r"(r[2]), "=r"(r[3]) : "r"(addr));
}
__device__ __forceinline__ void ldm_x4t(unsigned* r, uint32_t addr) {
    asm volatile("ldmatrix.sync.aligned.m8n8.x4.trans.shared.b16 {%0,%1,%2,%3}, [%4];"
        : "=r"(r[0]), "=r"(r[1]), "=r"(r[2]), "=r"(r[3]) : "r"(addr));
}

// cp.async 16B global -> shared
__device__ __forceinline__ void cp16(uint32_t dst, const void* src) {
    asm volatile("cp.async.cg.shared.global [%0], [%1], 16;"
        :: "r"(dst), "l"(__cvta_generic_to_global(src)) : "memory");
}
#define CP_COMMIT() asm volatile("cp.async.commit_group;" ::: "memory")
#define CP_WAIT1()  asm volatile("cp.async.wait_group 1;" ::: "memory")
#define CP_WAIT0()  asm volatile("cp.async.wait_group 0;" ::: "memory")

// pack two f32 -> f16x2 register (lo = first arg)
__device__ __forceinline__ unsigned pack_f162(float lo, float hi) {
    unsigned r;
    asm("cvt.rn.f16x2.f32 %0, %1, %2;" : "=r"(r) : "f"(hi), "f"(lo));
    return r;
}
__device__ __forceinline__ unsigned hsub2(unsigned a, unsigned b) {
    unsigned r;
    asm("sub.f16x2 %0, %1, %2;" : "=r"(r) : "r"(a), "r"(b));
    return r;
}
__device__ __forceinline__ unsigned ex2_f16x2(unsigned a) {
    unsigned r;
    asm("ex2.approx.f16x2 %0, %1;" : "=r"(r) : "r"(a));
    return r;
}

// ---------------------------------------------------------------------------
// LayerNorm -> fp16: warp-per-row, pure shuffle reduce
// ---------------------------------------------------------------------------
__global__ void ln_f16_kernel(const float* __restrict__ x,
                              const float* __restrict__ g,
                              const float* __restrict__ b,
                              f16* __restrict__ o) {
    int warp = threadIdx.x >> 5, lane = threadIdx.x & 31;
    int row = blockIdx.x * 4 + warp;
    const float4* xr = reinterpret_cast<const float4*>(x + (size_t)row * CC);

    float4 v[8];
    float s = 0.0f, ss = 0.0f;
    #pragma unroll
    for (int j = 0; j < 8; j++) {
        v[j] = xr[lane + j * 32];
        s  += v[j].x + v[j].y + v[j].z + v[j].w;
        ss += v[j].x * v[j].x + v[j].y * v[j].y + v[j].z * v[j].z + v[j].w * v[j].w;
    }
    #pragma unroll
    for (int of = 16; of > 0; of >>= 1) {
        s  += __shfl_xor_sync(0xFFFFFFFFu, s,  of);
        ss += __shfl_xor_sync(0xFFFFFFFFu, ss, of);
    }

    float mu  = s * (1.0f / CC);
    float var = ss * (1.0f / CC) - mu * mu;
    float inv = rsqrtf(var + 1e-5f);

    const float4* gr = reinterpret_cast<const float4*>(g);
    const float4* br = reinterpret_cast<const float4*>(b);
    uint2* op = reinterpret_cast<uint2*>(o + (size_t)row * CC);
    #pragma unroll
    for (int j = 0; j < 8; j++) {
        float4 gv = gr[lane + j * 32];
        float4 bv = br[lane + j * 32];
        float o0 = (v[j].x - mu) * inv * gv.x + bv.x;
        float o1 = (v[j].y - mu) * inv * gv.y + bv.y;
        float o2 = (v[j].z - mu) * inv * gv.z + bv.z;
        float o3 = (v[j].w - mu) * inv * gv.w + bv.w;
        op[lane + j * 32] = make_uint2(pack_f162(o0, o1), pack_f162(o2, o3));
    }
}

// ---------------------------------------------------------------------------
// Merged weight transpose: ONE launch covers w_qk, w_v, w_proj.
// Each block does one 32x32 transpose tile; blockIdx routing:
//   [0, 2048)        -> w_qk  [1024,2048] -> wT rows [0,2C)
//   [2048, 3072)     -> w_v   [1024,1024] -> wT rows [2C,3C)
//   [3072, 4096)     -> w_proj[1024,1024] -> wpT
// ---------------------------------------------------------------------------
__global__ void wsplit_all(const float* __restrict__ wqk,
                           const float* __restrict__ wv,
                           const float* __restrict__ wproj,
                           f16* __restrict__ wT,
                           f16* __restrict__ wpT) {
    __shared__ float t[32][33];
    int id = blockIdx.x;
    const float* src;
    f16* dst;
    int bx, by, N;
    if (id < 2048) {
        src = wqk; dst = wT; N = 2 * CC;
        bx = id & 63; by = id >> 6;
    } else if (id < 3072) {
        int id2 = id - 2048;
        src = wv; dst = wT + (size_t)2 * CC * CC; N = CC;
        bx = id2 & 31; by = id2 >> 5;
    } else {
        int id2 = id - 3072;
        src = wproj; dst = wpT; N = CC;
        bx = id2 & 31; by = id2 >> 5;
    }
    const int K = CC;

    int x = bx * 32 + threadIdx.x;
    #pragma unroll
    for (int j = 0; j < 32; j += 8)
        t[threadIdx.y + j][threadIdx.x] = src[(size_t)(by * 32 + threadIdx.y + j) * N + x];
    __syncthreads();
    int n = bx * 32 + threadIdx.y;
    int k = by * 32 + threadIdx.x;
    #pragma unroll
    for (int j = 0; j < 32; j += 8)
        dst[(size_t)(n + j) * K + k] = __float2half(t[threadIdx.x][threadIdx.y + j]);
}

// ---------------------------------------------------------------------------
// 1-pass fp16 GEMM (fp32 accumulate): C[M,N] = A[M,K] @ B[N,K]^T.
// MODE 0: fp32 out (+bias). MODE 2: fused qkv epilogue — cols [0,2C) -> Cq
// (xQSCALE for cols < C), cols [2C,3C) -> Cv at col-2C.
// CTA 128x128 tile, 8 warps (2x4), warp 64x32. K chunk 64 (4 k16 blocks,
// 64 MMAs/warp between syncs), cp.async DOUBLE buffer (R15 config: 73.7KB
// smem -> 2 CTAs/SM co-residency, which R16 proved load-bearing).
// Same ascending k16 accumulation order -> bit-identical results.
// ---------------------------------------------------------------------------
#define KCG 64
#define PADG 72
#define SBUF (128 * PADG)          // f16 elems per tensor-buffer
#define GSMEM (4 * SBUF * 2)       // bytes (73728) — 2 stages x (A,B)

template <int MODE>
__global__ void __launch_bounds__(256, 2)
gemm_f16(const f16* __restrict__ A, const f16* __restrict__ B,
         const float* __restrict__ bias, float* __restrict__ C,
         f16* __restrict__ Cq, f16* __restrict__ Cv,
         int M, int N, int K) {
    extern __shared__ f16 gsm[];
    const uint32_t sbase = smem_u32(gsm);

    int tid = threadIdx.x;
    int warp = tid >> 5, lane = tid & 31;
    int wm = warp >> 2, wn = warp & 3;
    int m0 = blockIdx.y * 128, n0 = blockIdx.x * 128;

    // cp.async mapping: 4 rows per thread per tensor (row = (tid>>3)+p*32)
    int lr = tid >> 3, lc = (tid & 7) * 8;

    float acc[4][4][4];
    #pragma unroll
    for (int i = 0; i < 4; i++)
        #pragma unroll
        for (int j = 0; j < 4; j++)
            #pragma unroll
            for (int q = 0; q < 4; q++) acc[i][j][q] = 0.0f;

    int a_row = wm * 64 + (lane & 15);
    int a_cb  = ((lane >> 4) & 1) * 16;
    int b_row = wn * 32 + ((lane >> 4) & 1) * 8 + (lane & 7);
    int b_cb  = ((lane >> 3) & 1) * 16;

    auto issue = [&](int c, int buf) {
        uint32_t bA = sbase + (uint32_t)buf * (SBUF * 2);
        uint32_t bB = sbase + (uint32_t)(2 + buf) * (SBUF * 2);
        #pragma unroll
        for (int p = 0; p < 4; p++) {
            int r = lr + p * 32;
            uint32_t so = (uint32_t)(r * PADG + lc) * 2;
            cp16(bA + so, A + (size_t)(m0 + r) * K + c * KCG + lc);
            cp16(bB + so, B + (size_t)(n0 + r) * K + c * KCG + lc);
        }
        CP_COMMIT();
    };

    issue(0, 0);

    int nch = K / KCG;
    #pragma unroll 1
    for (int c = 0; c < nch; c++) {
        int cur = c & 1;
        if (c + 1 < nch) {
            issue(c + 1, cur ^ 1);
            CP_WAIT1();
        } else {
            CP_WAIT0();
        }
        __syncthreads();

        uint32_t baseA = sbase + (uint32_t)cur * (SBUF * 2);
        uint32_t baseB = sbase + (uint32_t)(2 + cur) * (SBUF * 2);

        #pragma unroll
        for (int kk = 0; kk < 4; kk++) {
            unsigned fA[4][4], fB[4][2];
            #pragma unroll
            for (int np = 0; np < 2; np++) {
                unsigned r4[4];
                uint32_t ab = baseB + (uint32_t)(b_row + np * 16) * (PADG * 2)
                              + kk * 32 + b_cb;
                ldm_x4(r4, ab);
                fB[np * 2 + 0][0] = r4[0]; fB[np * 2 + 0][1] = r4[1];
                fB[np * 2 + 1][0] = r4[2]; fB[np * 2 + 1][1] = r4[3];
            }
            #pragma unroll
            for (int mt = 0; mt < 4; mt++)
                ldm_x4(fA[mt], baseA + (uint32_t)(a_row + mt * 16) * (PADG * 2)
                                + kk * 32 + a_cb);
            #pragma unroll
            for (int mt = 0; mt < 4; mt++)
                #pragma unroll
                for (int nt = 0; nt < 4; nt++)
                    mma_f16(acc[mt][nt], fA[mt], fB[nt]);
        }
        __syncthreads();
    }

    // epilogue
    #pragma unroll
    for (int mt = 0; mt < 4; mt++) {
        int row = m0 + wm * 64 + mt * 16 + (lane >> 2);
        #pragma unroll
        for (int nt = 0; nt < 4; nt++) {
            int col = n0 + wn * 32 + nt * 8 + (lane & 3) * 2;
            if (MODE == 2) {
                // fused qkv routing: [0,C)=q (xQSCALE), [C,2C)=k, [2C,3C)=v
                float sc = (col < CC) ? QSCALE : 1.0f;
                f16* dst;
                if (col < 2 * CC) dst = Cq + (size_t)row * (2 * CC) + col;
                else              dst = Cv + (size_t)row * CC + (col - 2 * CC);
                #pragma unroll
                for (int half = 0; half < 2; half++) {
                    float v0 = acc[mt][nt][half * 2 + 0] * sc;
                    float v1 = acc[mt][nt][half * 2 + 1] * sc;
                    *reinterpret_cast<unsigned*>(
                        dst + (size_t)(half * 8) * ((col < 2 * CC) ? 2 * CC : CC)) =
                        pack_f162(v0, v1);
                }
            } else {
                float bx = bias[col], by = bias[col + 1];
                float2 r0 = make_float2(acc[mt][nt][0] + bx, acc[mt][nt][1] + by);
                float2 r1 = make_float2(acc[mt][nt][2] + bx, acc[mt][nt][3] + by);
                *reinterpret_cast<float2*>(C + (size_t)row * N + col) = r0;
                *reinterpret_cast<float2*>(C + (size_t)(row + 8) * N + col) = r1;
            }
        }
    }
}

// ---------------------------------------------------------------------------
// Flash attention on tensor cores — fp16 operands, fp32 accumulate.
// log2-domain softmax (q pre-scaled 0.125*log2e), p = ex2.approx.f16x2,
// l via ones-column MMA. BQ=128, 4 warps. cp.async double buffer.
// (unchanged — at its mma.sync MMA floor)
// ---------------------------------------------------------------------------
#define APAD 72
#define KVB (2 * 64 * APAD)        // elems per K/V buffer (K | V)
#define ASMEM (2 * KVB * 2 + 16)   // bytes (+16: boundary ldmatrix guard)

__global__ void __launch_bounds__(128)
attn_mma(const f16* __restrict__ qkh, const f16* __restrict__ vp,
         float* __restrict__ out) {
    extern __shared__ f16 sm[];
    const uint32_t sb = smem_u32(sm);

    int qt = blockIdx.x, h = blockIdx.y, b = blockIdx.z;
    int tid = threadIdx.x, warp = tid >> 5, lane = tid & 31;
    int quad = lane >> 2;

    // --- stage Q (fp16, 128 rows) in smem; build persistent frags ---
    for (int i = tid; i < 128 * 8; i += 128) {
        int r = i >> 3, c8 = (i & 7) * 8;
        size_t grow = (size_t)(b * NN + qt * 128 + r) * (2 * CC) + h * HD + c8;
        *reinterpret_cast<uint4*>(&sm[r * APAD + c8]) =
            *reinterpret_cast<const uint4*>(qkh + grow);
    }
    __syncthreads();
    unsigned fQ[2][4][4];
    {
        int cb = ((lane >> 4) & 1) * 16;
        #pragma unroll
        for (int mt = 0; mt < 2; mt++) {
            int ar = warp * 32 + mt * 16 + (lane & 15);
            #pragma unroll
            for (int kk = 0; kk < 4; kk++)
                ldm_x4(fQ[mt][kk], sb + (uint32_t)(ar * APAD) * 2 + kk * 32 + cb);
        }
    }
    __syncthreads();

    // --- ones-column init: V rows col64=1.0, cols65-71=0, both buffers ---
    {
        int buf = tid >> 6, r = tid & 63;
        uint32_t addr = sb + (uint32_t)buf * (KVB * 2)
                        + (uint32_t)(64 * APAD + r * APAD + 64) * 2;
        asm volatile("st.shared.v4.b32 [%0], {%1,%2,%3,%4};"
            :: "r"(addr), "r"(0x00003C00u), "r"(0u), "r"(0u), "r"(0u) : "memory");
    }

    float O[2][8][4];
    #pragma unroll
    for (int mt = 0; mt < 2; mt++)
        #pragma unroll
        for (int nt = 0; nt < 8; nt++)
            #pragma unroll
            for (int q = 0; q < 4; q++) O[mt][nt][q] = 0.0f;
    float lacc[2][4];
    #pragma unroll
    for (int mt = 0; mt < 2; mt++)
        #pragma unroll
        for (int q = 0; q < 4; q++) lacc[mt][q] = 0.0f;
    float mS[2][2];
    #pragma unroll
    for (int mt = 0; mt < 2; mt++) { mS[mt][0] = -1e30f; mS[mt][1] = -1e30f; }

    int krow = tid >> 3, kcol = (tid & 7) * 8;

    int kb_row = ((lane >> 4) & 1) * 8 + (lane & 7);
    int kb_cb  = ((lane >> 3) & 1) * 16;
    int vb_row = ((lane >> 3) & 1) * 8 + (lane & 7);
    int vb_cb  = ((lane >> 4) & 1) * 16;

    auto kv_issue = [&](int it, int buf) {
        uint32_t base = sb + (uint32_t)buf * (KVB * 2);
        #pragma unroll
        for (int rr = 0; rr < 64; rr += 16) {
            int r = krow + rr;
            size_t gk = (size_t)(b * NN + it * 64 + r) * (2 * CC) + CC + h * HD + kcol;
            size_t gv = (size_t)(b * NN + it * 64 + r) * CC + h * HD + kcol;
            cp16(base + (uint32_t)(0 * 64 * APAD + r * APAD + kcol) * 2, qkh + gk);
            cp16(base + (uint32_t)(1 * 64 * APAD + r * APAD + kcol) * 2, vp + gv);
        }
        CP_COMMIT();
    };

    kv_issue(0, 0);

    const int NIT = NN / 64;
    #pragma unroll 1
    for (int it = 0; it < NIT; it++) {
        int cur = it & 1;
        if (it + 1 < NIT) {
            kv_issue(it + 1, cur ^ 1);
            CP_WAIT1();
        } else {
            CP_WAIT0();
        }
        __syncthreads();

        uint32_t base = sb + (uint32_t)cur * (KVB * 2);
        uint32_t sKh = base;
        uint32_t sVh = base + 1 * 64 * APAD * 2;

        // ---- S = Q @ K^T (1 pass, fp16; K frags shared across 2 m-tiles) ----
        float S[2][8][4];
        #pragma unroll
        for (int mt = 0; mt < 2; mt++)
            #pragma unroll
            for (int nt = 0; nt < 8; nt++)
                #pragma unroll
                for (int q = 0; q < 4; q++) S[mt][nt][q] = 0.0f;

        #pragma unroll
        for (int kk = 0; kk < 4; kk++) {
            unsigned fKh[8][2];
            #pragma unroll
            for (int np = 0; np < 4; np++) {
                unsigned r4[4];
                uint32_t off = (uint32_t)(kb_row + np * 16) * (APAD * 2) + kb_cb + kk * 32;
                ldm_x4(r4, sKh + off);
                fKh[np * 2 + 0][0] = r4[0]; fKh[np * 2 + 0][1] = r4[1];
                fKh[np * 2 + 1][0] = r4[2]; fKh[np * 2 + 1][1] = r4[3];
            }
            #pragma unroll
            for (int mt = 0; mt < 2; mt++)
                #pragma unroll
                for (int nt = 0; nt < 8; nt++)
                    mma_f16(S[mt][nt], fQ[mt][kk], fKh[nt]);
        }

        // ---- log2-domain softmax + fp16x2 exp + pack P ----
        unsigned Phi[2][8][2];
        #pragma unroll
        for (int mt = 0; mt < 2; mt++) {
            float mx0 = -1e30f, mx1 = -1e30f;
            #pragma unroll
            for (int nt = 0; nt < 8; nt++) {
                mx0 = fmaxf(mx0, fmaxf(S[mt][nt][0], S[mt][nt][1]));
                mx1 = fmaxf(mx1, fmaxf(S[mt][nt][2], S[mt][nt][3]));
            }
            mx0 = fmaxf(mx0, __shfl_xor_sync(0xFFFFFFFFu, mx0, 1));
            mx0 = fmaxf(mx0, __shfl_xor_sync(0xFFFFFFFFu, mx0, 2));
            mx1 = fmaxf(mx1, __shfl_xor_sync(0xFFFFFFFFu, mx1, 1));
            mx1 = fmaxf(mx1, __shfl_xor_sync(0xFFFFFFFFu, mx1, 2));
            float mn0 = fmaxf(mS[mt][0], mx0), mn1 = fmaxf(mS[mt][1], mx1);
            float al0 = exp2f(mS[mt][0] - mn0), al1 = exp2f(mS[mt][1] - mn1);
            mS[mt][0] = mn0; mS[mt][1] = mn1;

            unsigned m00 = pack_f162(mn0, mn0);
            unsigned m11 = pack_f162(mn1, mn1);

            #pragma unroll
            for (int nt = 0; nt < 8; nt++) {
                O[mt][nt][0] *= al0; O[mt][nt][1] *= al0;
                O[mt][nt][2] *= al1; O[mt][nt][3] *= al1;
            }
            lacc[mt][0] *= al0; lacc[mt][1] *= al0;
            lacc[mt][2] *= al1; lacc[mt][3] *= al1;

            #pragma unroll
            for (int nt = 0; nt < 8; nt++) {
                unsigned s01 = pack_f162(S[mt][nt][0], S[mt][nt][1]);
                unsigned s23 = pack_f162(S[mt][nt][2], S[mt][nt][3]);
                Phi[mt][nt][0] = ex2_f16x2(hsub2(s01, m00));
                Phi[mt][nt][1] = ex2_f16x2(hsub2(s23, m11));
            }
        }

        // ---- O += P @ V; l += P @ ones (fp16 MMA; V frags shared) ----
        #pragma unroll
        for (int kk = 0; kk < 4; kk++) {
            unsigned fVh[8][2], fL[2];
            #pragma unroll
            for (int nt2 = 0; nt2 < 4; nt2++) {
                unsigned r4[4];
                uint32_t off = (uint32_t)(vb_row + kk * 16) * (APAD * 2) + vb_cb + nt2 * 32;
                ldm_x4t(r4, sVh + off);
                fVh[nt2 * 2 + 0][0] = r4[0]; fVh[nt2 * 2 + 0][1] = r4[1];
                fVh[nt2 * 2 + 1][0] = r4[2]; fVh[nt2 * 2 + 1][1] = r4[3];
            }
            {
                unsigned r4[4];
                uint32_t off = (uint32_t)(vb_row + kk * 16) * (APAD * 2) + vb_cb + 4 * 32;
                ldm_x4t(r4, sVh + off);
                fL[0] = r4[0]; fL[1] = r4[1];   // cols 64-71 (ones | zeros)
            }
            #pragma unroll
            for (int mt = 0; mt < 2; mt++) {
                unsigned aPh[4] = {Phi[mt][2 * kk][0], Phi[mt][2 * kk][1],
                                   Phi[mt][2 * kk + 1][0], Phi[mt][2 * kk + 1][1]};
                #pragma unroll
                for (int nt = 0; nt < 8; nt++)
                    mma_f16(O[mt][nt], aPh, fVh[nt]);
                mma_f16(lacc[mt], aPh, fL);
            }
        }
        __syncthreads();
    }

    // ---- finalize & store (l lives in tq=0 lanes' c0/c2) ----
    #pragma unroll
    for (int mt = 0; mt < 2; mt++) {
        float l0 = __shfl_sync(0xFFFFFFFFu, lacc[mt][0], lane & 28);
        float l1 = __shfl_sync(0xFFFFFFFFu, lacc[mt][2], lane & 28);
        float inv0 = 1.0f / l0, inv1 = 1.0f / l1;
        int row0 = b * NN + qt * 128 + warp * 32 + mt * 16 + quad;
        #pragma unroll
        for (int nt = 0; nt < 8; nt++) {
            int col = h * HD + nt * 8 + (lane & 3) * 2;
            *reinterpret_cast<float2*>(out + (size_t)row0 * CC + col) =
                make_float2(O[mt][nt][0] * inv0, O[mt][nt][1] * inv0);
            *reinterpret_cast<float2*>(out + (size_t)(row0 + 8) * CC + col) =
                make_float2(O[mt][nt][2] * inv1, O[mt][nt][3] * inv1);
        }
    }
}

// ---------------------------------------------------------------------------
extern "C" void kernel_launch(void* const* d_in, const int* in_sizes, int n_in,
                              void* d_out, int out_size) {
    const float* x      = (const float*)d_in[0];
    const float* ln1_g  = (const float*)d_in[1];
    const float* ln1_b  = (const float*)d_in[2];
    const float* w_qk   = (const float*)d_in[3];
    const float* w_v    = (const float*)d_in[4];
    const float* ln2_g  = (const float*)d_in[5];
    const float* ln2_b  = (const float*)d_in[6];
    const float* w_proj = (const float*)d_in[7];
    const float* b_proj = (const float*)d_in[8];
    float* out = (float*)d_out;

    float* ao;
    f16 *xf, *qkh, *vp, *wT, *wpT;
    cudaGetSymbolAddress((void**)&ao,   g_ao);
    cudaGetSymbolAddress((void**)&xf,   g_xf);
    cudaGetSymbolAddress((void**)&qkh,  g_qkh);
    cudaGetSymbolAddress((void**)&vp,   g_v);
    cudaGetSymbolAddress((void**)&wT,   g_wT);
    cudaGetSymbolAddress((void**)&wpT,  g_wpT);

    cudaFuncSetAttribute(attn_mma, cudaFuncAttributeMaxDynamicSharedMemorySize, ASMEM);
    cudaFuncSetAttribute(gemm_f16<2>, cudaFuncAttributeMaxDynamicSharedMemorySize, GSMEM);
    cudaFuncSetAttribute(gemm_f16<0>, cudaFuncAttributeMaxDynamicSharedMemorySize, GSMEM);

    // merged weight transpose (one launch for all three weights)
    wsplit_all<<<4096, dim3(32, 8)>>>(w_qk, w_v, w_proj, wT, wpT);

    // 1. LN1 -> fp16 (warp-per-row)
    ln_f16_kernel<<<MM / 4, 128>>>(x, ln1_g, ln1_b, xf);

    // 2. fused qkv projection (1-pass fp16; q pre-scaled by 0.125*log2e)
    gemm_f16<2><<<dim3(3 * CC / 128, MM / 128), 256, GSMEM>>>(
        xf, wT, nullptr, nullptr, qkh, vp, MM, 3 * CC, CC);

    // 3. tensor-core flash attention (log2-softmax, f16x2 exp, MMA-computed l)
    attn_mma<<<dim3(NN / 128, HH, BB), 128, ASMEM>>>(qkh, vp, ao);

    // 4. LN2 -> fp16
    ln_f16_kernel<<<MM / 4, 128>>>(ao, ln2_g, ln2_b, xf);

    // 5. output projection + bias (1-pass fp16, fp32 out)
    gemm_f16<0><<<dim3(CC / 128, MM / 128), 256, GSMEM>>>(
        xf, wpT, b_proj, out, nullptr, nullptr, MM, CC, CC);
}